// round 6
// baseline (speedup 1.0000x reference)
#include <cuda_runtime.h>

// DifferentiableBezierRenderer — separable winding + sigmoid-saturation
// difference-array formulation.
//
// wind[y][gx] = sum_e c_e(y) * sigmoid(xc_e(y) - gx)
//   c, xc depend only on (edge,row). sigmoid saturates: step + 41-col band.
//
// K1: zero scratch + sample bezier (2048 pts)
// K2: per (edge,row): scatter step into diff-array D, exact band into B
// K3: per row: inclusive scan of D + B, alpha = sigmoid(4*wind), write RGBA

#define HH 512
#define WW 512
#define MM 2048           // 64 segments * 32 samples
#define T_BAND 20.0f      // sigmoid saturation cutoff (e^-20 ~ 2e-9)

__device__ float g_px[MM];
__device__ float g_py[MM];
__device__ float g_D[HH * WW];   // difference array (prefix-summed per row)
__device__ float g_B[HH * WW];   // exact transition-band accumulator

__device__ __forceinline__ float sigm(float z) {
    return 1.0f / (1.0f + __expf(-z));
}

// ---------------------------------------------------------------------------
// K1: zero D/B, sample cubic bezier points
// ---------------------------------------------------------------------------
__global__ void k_init(const float* __restrict__ cp) {
    int idx = blockIdx.x * blockDim.x + threadIdx.x;
    if (idx < HH * WW) {
        g_D[idx] = 0.0f;
        g_B[idx] = 0.0f;
    }
    if (idx < MM) {
        int s = idx >> 5;        // segment
        int i = idx & 31;        // sample
        float t  = (float)i / 31.0f;
        float mt = 1.0f - t;
        float w0 = mt * mt * mt;
        float w1 = 3.0f * mt * mt * t;
        float w2 = 3.0f * mt * t * t;
        float w3 = t * t * t;
        const float* c0 = cp + 6 * s;   // cp[3s], interleaved (x,y)
        g_px[idx] = w0 * c0[0] + w1 * c0[2] + w2 * c0[4] + w3 * c0[6];
        g_py[idx] = w0 * c0[1] + w1 * c0[3] + w2 * c0[5] + w3 * c0[7];
    }
}

// ---------------------------------------------------------------------------
// K2: one block per edge, one thread per row.
// ---------------------------------------------------------------------------
__global__ void k_scatter() {
    int e = blockIdx.x;
    int y = threadIdx.x;
    int e1 = (e + 1) & (MM - 1);

    float x0 = g_px[e],  y0 = g_py[e];
    float x1 = g_px[e1], y1 = g_py[e1];
    float dy = y1 - y0;
    if (fabsf(dy) < 1e-6f) return;              // reference mask

    float t = ((float)y - y0) / (dy + 1e-8f);   // reference's exact formula
    float c = sigm(20.0f * t) * sigm(20.0f * (1.0f - t));   // valid_t
    if (c < 1e-9f) return;                      // negligible contribution
    if (dy < 0.0f) c = -c;                      // * sign(dy)

    float xc = x0 + t * (x1 - x0);

    int gL = (int)ceilf(xc - T_BAND);
    int gR = (int)floorf(xc + T_BAND);

    // Step part: contribution c for gx in [0, jl)
    int jl = gL < 0 ? 0 : (gL > WW ? WW : gL);
    if (jl > 0) {
        atomicAdd(&g_D[y * WW], c);
        if (jl < WW) atomicAdd(&g_D[y * WW + jl], -c);
    }

    // Exact band: c * sigmoid(xc - gx) for gx in [gL, gR] ∩ [0, W)
    int b0 = gL < 0 ? 0 : gL;
    int b1 = gR > WW - 1 ? WW - 1 : gR;
    for (int gx = b0; gx <= b1; ++gx) {
        atomicAdd(&g_B[y * WW + gx], c * sigm(xc - (float)gx));
    }
}

// ---------------------------------------------------------------------------
// K3: one block per row (512 threads). Inclusive scan of D + band, write RGBA.
// ---------------------------------------------------------------------------
__global__ void k_resolve(const float* __restrict__ color,
                          float* __restrict__ out) {
    int row  = blockIdx.x;
    int tid  = threadIdx.x;
    int lane = tid & 31;
    int wid  = tid >> 5;

    float v = g_D[row * WW + tid];

    // inclusive warp scan
    #pragma unroll
    for (int o = 1; o < 32; o <<= 1) {
        float n = __shfl_up_sync(0xffffffffu, v, o);
        if (lane >= o) v += n;
    }

    __shared__ float wsum[16];
    if (lane == 31) wsum[wid] = v;
    __syncthreads();

    if (wid == 0) {
        float w = (lane < 16) ? wsum[lane] : 0.0f;
        #pragma unroll
        for (int o = 1; o < 16; o <<= 1) {
            float n = __shfl_up_sync(0xffffffffu, w, o);
            if (lane >= o) w += n;
        }
        if (lane < 16) wsum[lane] = w;
    }
    __syncthreads();

    float prefix = (wid > 0) ? wsum[wid - 1] : 0.0f;
    float wind   = v + prefix + g_B[row * WW + tid];
    float alpha  = 1.0f / (1.0f + __expf(-4.0f * wind));

    float4 px = make_float4(color[0], color[1], color[2], alpha);
    reinterpret_cast<float4*>(out)[row * WW + tid] = px;
}

// ---------------------------------------------------------------------------
extern "C" void kernel_launch(void* const* d_in, const int* in_sizes, int n_in,
                              void* d_out, int out_size) {
    const float* cp    = (const float*)d_in[0];   // (193,2) f32
    const float* color = (const float*)d_in[1];   // (3,)   f32
    float* out = (float*)d_out;                   // (512,512,4) f32

    k_init<<<(HH * WW + 255) / 256, 256>>>(cp);
    k_scatter<<<MM, HH>>>();
    k_resolve<<<HH, WW>>>(color, out);
}